// round 4
// baseline (speedup 1.0000x reference)
#include <cuda_runtime.h>
#include <math.h>

#define BB 4
#define NN 300
#define CC 80
#define KK 17
#define WW 64
#define HW 4096
#define NEGV (-1000000000.0f)

// scratch: per-(b,n,k) keypoint (nx, ny, maxval)
__device__ float g_kpts[BB * NN * KK * 3];

// ---------------------------------------------------------------------------
// Kernel 1: per-heatmap argmax + keypoint normalize. One CTA per (b,n,k).
// 128 threads x 8 float4 = 4096 floats, fully coalesced, MLP=8.
// ---------------------------------------------------------------------------
__global__ __launch_bounds__(128) void hm_kernel(const float* __restrict__ hm,
                                                 const float* __restrict__ off) {
    int bid = blockIdx.x;  // (b*NN + n)*KK + k
    const float4* p4 = (const float4*)(hm + (size_t)bid * HW);
    int t = threadIdx.x;

    float best = -INFINITY;
    int bi = 0x7fffffff;
#pragma unroll
    for (int i = 0; i < 8; i++) {
        float4 v = p4[i * 128 + t];
        int base = (i * 128 + t) * 4;
        if (v.x > best) { best = v.x; bi = base; }
        if (v.y > best) { best = v.y; bi = base + 1; }
        if (v.z > best) { best = v.z; bi = base + 2; }
        if (v.w > best) { best = v.w; bi = base + 3; }
    }
    // warp argmax reduce (tie -> lowest index, matching jnp.argmax)
#pragma unroll
    for (int o = 16; o > 0; o >>= 1) {
        float ov = __shfl_down_sync(0xffffffffu, best, o);
        int oi = __shfl_down_sync(0xffffffffu, bi, o);
        if (ov > best || (ov == best && oi < bi)) { best = ov; bi = oi; }
    }
    __shared__ float sv[4];
    __shared__ int si[4];
    if ((t & 31) == 0) { sv[t >> 5] = best; si[t >> 5] = bi; }
    __syncthreads();
    if (t == 0) {
        for (int i = 1; i < 4; i++)
            if (sv[i] > best || (sv[i] == best && si[i] < bi)) { best = sv[i]; bi = si[i]; }
        float ox = off[2 * bid], oy = off[2 * bid + 1];
        float nx = fminf(fmaxf((float)(bi & 63) / 63.0f + ox, 0.0f), 1.0f);
        float ny = fminf(fmaxf((float)(bi >> 6) / 63.0f + oy, 0.0f), 1.0f);
        g_kpts[3 * bid + 0] = nx;
        g_kpts[3 * bid + 1] = ny;
        g_kpts[3 * bid + 2] = best;
    }
}

// ---------------------------------------------------------------------------
// Kernel 2: fused scores/labels/boxes + class-aware NMS + output gather.
// One CTA per batch (B=4), 512 threads.
// Exploits TOPK == N == 300: output = kept dets in score order, then padding.
// ---------------------------------------------------------------------------
__global__ __launch_bounds__(512) void nms_kernel(const float* __restrict__ logits,
                                                  const float* __restrict__ boxes,
                                                  const float* __restrict__ sizes,
                                                  float* __restrict__ out) {
    int b = blockIdx.x;
    int t = threadIdx.x;

    __shared__ float s_score[NN];      // sigmoid score, orig order
    __shared__ int s_lab[NN];          // argmax label, orig order
    __shared__ float s_box[NN][4];     // abs xyxy, orig order
    __shared__ float s_s[NN];          // masked score (NEG if invalid)
    __shared__ int s_order[NN];        // sorted pos -> orig idx
    __shared__ unsigned s_mask[NN * 10];  // IoU>thr bit rows (sorted space)
    __shared__ int s_list[NN];         // output slot -> sorted pos (kept)
    __shared__ float s_red[16];
    __shared__ float s_maxc;
    __shared__ int s_M;

    // --- scores, labels, abs boxes ---
    float lm = 0.0f;
    if (t < NN) {
        const float* lp = logits + ((size_t)b * NN + t) * CC;
        float mv = lp[0];
        int ml = 0;
        for (int c = 1; c < CC; c++) {
            float v = lp[c];
            if (v > mv) { mv = v; ml = c; }
        }
        float sc = 1.0f / (1.0f + expf(-mv));
        s_score[t] = sc;
        s_lab[t] = ml;
        const float* bp = boxes + ((size_t)b * NN + t) * 4;
        float cx = bp[0], cy = bp[1], w = bp[2], h = bp[3];
        float sx = sizes[2 * b], sy = sizes[2 * b + 1];
        float x1 = (cx - w * 0.5f) * sx;
        float y1 = (cy - h * 0.5f) * sy;
        float x2 = (cx + w * 0.5f) * sx;
        float y2 = (cy + h * 0.5f) * sy;
        s_box[t][0] = x1; s_box[t][1] = y1; s_box[t][2] = x2; s_box[t][3] = y2;
        s_s[t] = (sc > 0.01f) ? sc : NEGV;
        lm = fmaxf(fmaxf(fabsf(x1), fabsf(y1)), fmaxf(fabsf(x2), fabsf(y2)));
    }
    // block max |coord|
#pragma unroll
    for (int o = 16; o > 0; o >>= 1) lm = fmaxf(lm, __shfl_down_sync(0xffffffffu, lm, o));
    if ((t & 31) == 0) s_red[t >> 5] = lm;
    __syncthreads();
    if (t == 0) {
        float m = s_red[0];
        for (int i = 1; i < 16; i++) m = fmaxf(m, s_red[i]);
        s_maxc = m + 1.0f;
    }
    __syncthreads();

    // --- stable descending rank sort (matches jnp.argsort(-s)) ---
    if (t < NN) {
        float sj = s_s[t];
        int r = 0;
        for (int i = 0; i < NN; i++) {
            float si_ = s_s[i];
            r += (si_ > sj) || (si_ == sj && i < t);
        }
        s_order[r] = t;
    }
    __syncthreads();

    // --- IoU > 0.7 bit matrix in sorted space (class-offset boxes) ---
    float maxc = s_maxc;
    for (int task = t; task < NN * 10; task += 512) {
        int i = task / 10, w = task % 10;
        int oi = s_order[i];
        float off_i = (float)s_lab[oi] * maxc;
        float ix1 = s_box[oi][0] + off_i, iy1 = s_box[oi][1] + off_i;
        float ix2 = s_box[oi][2] + off_i, iy2 = s_box[oi][3] + off_i;
        float ia = (ix2 - ix1) * (iy2 - iy1);
        unsigned word = 0;
        int jbase = w * 32;
        for (int bit = 0; bit < 32; bit++) {
            int j = jbase + bit;
            if (j >= NN || j == i) continue;
            int oj = s_order[j];
            float off_j = (float)s_lab[oj] * maxc;
            float jx1 = s_box[oj][0] + off_j, jy1 = s_box[oj][1] + off_j;
            float jx2 = s_box[oj][2] + off_j, jy2 = s_box[oj][3] + off_j;
            float ja = (jx2 - jx1) * (jy2 - jy1);
            float iw = fmaxf(fminf(ix2, jx2) - fmaxf(ix1, jx1), 0.0f);
            float ih = fmaxf(fminf(iy2, jy2) - fmaxf(iy1, jy1), 0.0f);
            float inter = iw * ih;
            float iou = inter / (ia + ja - inter + 1e-9f);
            if (iou > 0.7f) word |= (1u << bit);
        }
        s_mask[i * 10 + w] = word;
    }
    __syncthreads();

    // --- greedy NMS: single warp, register suppression words, no barriers ---
    if (t < 32) {
        unsigned supp = 0, validw = 0;
        if (t < 10) {
            for (int bit = 0; bit < 32; bit++) {
                int j = t * 32 + bit;
                if (j < NN && s_score[s_order[j]] > 0.01f) validw |= (1u << bit);
            }
        }
        int m = 0;
        for (int i = 0; i < NN; i++) {
            int owner = i >> 5, bit = i & 31;
            unsigned sw_ = __shfl_sync(0xffffffffu, supp, owner);
            unsigned vw_ = __shfl_sync(0xffffffffu, validw, owner);
            bool keep = ((vw_ >> bit) & 1u) && !((sw_ >> bit) & 1u);
            if (keep) {  // uniform across the warp -> shfl-safe
                if (t < 10) supp |= s_mask[i * 10 + t];
                if (t == 0) s_list[m] = i;
                m++;
            }
        }
        if (t == 0) s_M = m;
    }
    __syncthreads();
    int M = s_M;

    // --- outputs: [fl | fb | fs | akpts | vkeep], all float32 ---
    const int OUT_FB = BB * NN;                 // 1200
    const int OUT_FS = OUT_FB + BB * NN * 4;    // 6000
    const int OUT_KP = OUT_FS + BB * NN;        // 7200
    const int OUT_VK = OUT_KP + BB * NN * KK * 3;  // 68400

    if (t < NN) {
        int p = t;
        if (p < M) {
            int orig = s_order[s_list[p]];
            out[b * NN + p] = (float)s_lab[orig];
            out[OUT_FS + b * NN + p] = s_score[orig];
            out[OUT_VK + b * NN + p] = 1.0f;
            out[OUT_FB + (b * NN + p) * 4 + 0] = s_box[orig][0];
            out[OUT_FB + (b * NN + p) * 4 + 1] = s_box[orig][1];
            out[OUT_FB + (b * NN + p) * 4 + 2] = s_box[orig][2];
            out[OUT_FB + (b * NN + p) * 4 + 3] = s_box[orig][3];
        } else {
            out[b * NN + p] = -1.0f;
            out[OUT_FS + b * NN + p] = 0.0f;
            out[OUT_VK + b * NN + p] = 0.0f;
            out[OUT_FB + (b * NN + p) * 4 + 0] = 0.0f;
            out[OUT_FB + (b * NN + p) * 4 + 1] = 0.0f;
            out[OUT_FB + (b * NN + p) * 4 + 2] = 0.0f;
            out[OUT_FB + (b * NN + p) * 4 + 3] = 0.0f;
        }
    }
    // keypoints: slot p, joint k, component c
    for (int idx = t; idx < NN * KK * 3; idx += 512) {
        int p = idx / (KK * 3);
        int r = idx % (KK * 3);
        float val = 0.0f;
        if (p < M) {
            int orig = s_order[s_list[p]];
            int k = r / 3, c = r % 3;
            float kv = g_kpts[(((size_t)b * NN + orig) * KK + k) * 3 + c];
            if (c == 0) {
                float x1 = s_box[orig][0], x2 = s_box[orig][2];
                val = x1 + kv * (x2 - x1);
            } else if (c == 1) {
                float y1 = s_box[orig][1], y2 = s_box[orig][3];
                val = y1 + kv * (y2 - y1);
            } else {
                val = kv;
            }
        }
        out[OUT_KP + (size_t)b * NN * KK * 3 + idx] = val;
    }
}

extern "C" void kernel_launch(void* const* d_in, const int* in_sizes, int n_in,
                              void* d_out, int out_size) {
    const float* logits = (const float*)d_in[0];   // (4,300,80)
    const float* boxes = (const float*)d_in[1];    // (4,300,4)
    const float* hm = (const float*)d_in[2];       // (4,300,17,64,64)
    const float* off = (const float*)d_in[3];      // (4,300,17,2)
    const float* sizes = (const float*)d_in[4];    // (4,2)
    float* out = (float*)d_out;

    hm_kernel<<<BB * NN * KK, 128>>>(hm, off);
    nms_kernel<<<BB, 512>>>(logits, boxes, sizes, out);
}

// round 5
// speedup vs baseline: 1.5975x; 1.5975x over previous
#include <cuda_runtime.h>
#include <math.h>

#define BB 4
#define NN 300
#define CC 80
#define KK 17
#define HW 4096
#define NEGV (-1000000000.0f)

// ---- scratch (__device__ globals; no allocs allowed) ----
__device__ float    g_kpts[BB * NN * KK * 3];  // (nx, ny, maxval) per (b,n,k)
__device__ int      g_maxc_i[BB];              // per-batch max|coord| as int bits
__device__ float    g_score[BB * NN];
__device__ int      g_lab[BB * NN];
__device__ float    g_box[BB * NN * 4];
__device__ float    g_sscore[BB * NN];         // sorted, NEG-masked
__device__ int      g_slab[BB * NN];
__device__ float    g_sbox[BB * NN * 4];
__device__ int      g_sorder[BB * NN];         // sorted pos -> orig idx
__device__ unsigned g_mask[BB * NN * 10];      // IoU>0.7 bit rows, sorted space

// ---------------------------------------------------------------------------
// Kernel 1: per-heatmap argmax + keypoint normalize. One CTA per (b,n,k).
// 128 threads x 8 float4 = 4096 floats, fully coalesced. ~DRAM roofline.
// Also zero-inits g_maxc_i (block 0) for the later atomicMax.
// ---------------------------------------------------------------------------
__global__ __launch_bounds__(128) void hm_kernel(const float* __restrict__ hm,
                                                 const float* __restrict__ off) {
    int bid = blockIdx.x;  // (b*NN + n)*KK + k
    int t = threadIdx.x;
    if (bid == 0 && t < BB) g_maxc_i[t] = 0;

    const float4* p4 = (const float4*)(hm + (size_t)bid * HW);
    float best = -INFINITY;
    int bi = 0x7fffffff;
#pragma unroll
    for (int i = 0; i < 8; i++) {
        float4 v = p4[i * 128 + t];
        int base = (i * 128 + t) * 4;
        if (v.x > best) { best = v.x; bi = base; }
        if (v.y > best) { best = v.y; bi = base + 1; }
        if (v.z > best) { best = v.z; bi = base + 2; }
        if (v.w > best) { best = v.w; bi = base + 3; }
    }
#pragma unroll
    for (int o = 16; o > 0; o >>= 1) {
        float ov = __shfl_down_sync(0xffffffffu, best, o);
        int oi = __shfl_down_sync(0xffffffffu, bi, o);
        if (ov > best || (ov == best && oi < bi)) { best = ov; bi = oi; }
    }
    __shared__ float sv[4];
    __shared__ int si[4];
    if ((t & 31) == 0) { sv[t >> 5] = best; si[t >> 5] = bi; }
    __syncthreads();
    if (t == 0) {
        for (int i = 1; i < 4; i++)
            if (sv[i] > best || (sv[i] == best && si[i] < bi)) { best = sv[i]; bi = si[i]; }
        float ox = off[2 * bid], oy = off[2 * bid + 1];
        float nx = fminf(fmaxf((float)(bi & 63) / 63.0f + ox, 0.0f), 1.0f);
        float ny = fminf(fmaxf((float)(bi >> 6) / 63.0f + oy, 0.0f), 1.0f);
        g_kpts[3 * bid + 0] = nx;
        g_kpts[3 * bid + 1] = ny;
        g_kpts[3 * bid + 2] = best;
    }
}

// ---------------------------------------------------------------------------
// Kernel 2: prep — one WARP per detection. Coalesced logit argmax, sigmoid,
// abs box, per-batch atomicMax(|coord|).
// ---------------------------------------------------------------------------
__global__ __launch_bounds__(256) void prep_kernel(const float* __restrict__ logits,
                                                   const float* __restrict__ boxes,
                                                   const float* __restrict__ sizes) {
    int det = blockIdx.x * 8 + (threadIdx.x >> 5);
    int lane = threadIdx.x & 31;
    if (det >= BB * NN) return;

    const float* lp = logits + (size_t)det * CC;
    float best = -INFINITY;
    int bi = 0x7fffffff;
    for (int c = lane; c < CC; c += 32) {  // ascending c -> lowest-index tie-break
        float v = lp[c];
        if (v > best) { best = v; bi = c; }
    }
#pragma unroll
    for (int o = 16; o > 0; o >>= 1) {
        float ov = __shfl_down_sync(0xffffffffu, best, o);
        int oi = __shfl_down_sync(0xffffffffu, bi, o);
        if (ov > best || (ov == best && oi < bi)) { best = ov; bi = oi; }
    }
    if (lane == 0) {
        int b = det / NN;
        g_score[det] = 1.0f / (1.0f + expf(-best));
        g_lab[det] = bi;
        const float* bp = boxes + (size_t)det * 4;
        float cx = bp[0], cy = bp[1], w = bp[2], h = bp[3];
        float sx = sizes[2 * b], sy = sizes[2 * b + 1];
        float x1 = (cx - w * 0.5f) * sx;
        float y1 = (cy - h * 0.5f) * sy;
        float x2 = (cx + w * 0.5f) * sx;
        float y2 = (cy + h * 0.5f) * sy;
        g_box[det * 4 + 0] = x1; g_box[det * 4 + 1] = y1;
        g_box[det * 4 + 2] = x2; g_box[det * 4 + 3] = y2;
        float lm = fmaxf(fmaxf(fabsf(x1), fabsf(y1)), fmaxf(fabsf(x2), fabsf(y2)));
        atomicMax(&g_maxc_i[b], __float_as_int(lm));  // valid: lm >= 0
    }
}

// ---------------------------------------------------------------------------
// Kernel 3: stable descending rank sort per batch; scatter sorted arrays.
// ---------------------------------------------------------------------------
__global__ __launch_bounds__(512) void sort_kernel() {
    int b = blockIdx.x, t = threadIdx.x;
    __shared__ float s_s[NN];
    if (t < NN) {
        float sc = g_score[b * NN + t];
        s_s[t] = (sc > 0.01f) ? sc : NEGV;
    }
    __syncthreads();
    if (t < NN) {
        float sj = s_s[t];
        int r = 0;
        for (int i = 0; i < NN; i++) {
            float si_ = s_s[i];
            r += (si_ > sj) || (si_ == sj && i < t);  // stable, matches argsort(-s)
        }
        int src = b * NN + t, dst = b * NN + r;
        g_sorder[dst] = t;
        g_sscore[dst] = sj;
        g_slab[dst] = g_lab[src];
        g_sbox[dst * 4 + 0] = g_box[src * 4 + 0];
        g_sbox[dst * 4 + 1] = g_box[src * 4 + 1];
        g_sbox[dst * 4 + 2] = g_box[src * 4 + 2];
        g_sbox[dst * 4 + 3] = g_box[src * 4 + 3];
    }
}

// ---------------------------------------------------------------------------
// Kernel 4: IoU>0.7 bit matrix. One CTA per (b, row i), thread=j, ballot->word.
// ---------------------------------------------------------------------------
__global__ __launch_bounds__(320) void iou_kernel() {
    int b = blockIdx.x / NN, i = blockIdx.x % NN;
    int t = threadIdx.x, lane = t & 31, w = t >> 5;

    float maxc = __int_as_float(g_maxc_i[b]) + 1.0f;
    int base = b * NN;
    float offi = (float)g_slab[base + i] * maxc;
    float ix1 = g_sbox[(base + i) * 4 + 0] + offi;
    float iy1 = g_sbox[(base + i) * 4 + 1] + offi;
    float ix2 = g_sbox[(base + i) * 4 + 2] + offi;
    float iy2 = g_sbox[(base + i) * 4 + 3] + offi;
    float ia = (ix2 - ix1) * (iy2 - iy1);

    unsigned pred = 0;
    int j = t;
    if (j < NN && j != i) {
        float offj = (float)g_slab[base + j] * maxc;
        float jx1 = g_sbox[(base + j) * 4 + 0] + offj;
        float jy1 = g_sbox[(base + j) * 4 + 1] + offj;
        float jx2 = g_sbox[(base + j) * 4 + 2] + offj;
        float jy2 = g_sbox[(base + j) * 4 + 3] + offj;
        float ja = (jx2 - jx1) * (jy2 - jy1);
        float iw = fmaxf(fminf(ix2, jx2) - fmaxf(ix1, jx1), 0.0f);
        float ih = fmaxf(fminf(iy2, jy2) - fmaxf(iy1, jy1), 0.0f);
        float inter = iw * ih;
        float iou = inter / (ia + ja - inter + 1e-9f);
        pred = iou > 0.7f;
    }
    unsigned word = __ballot_sync(0xffffffffu, pred);
    if (lane == 0) g_mask[(base + i) * 10 + w] = word;
}

// ---------------------------------------------------------------------------
// Kernel 5: greedy NMS (single-thread remaining-bitmask scan) + output gather.
// One CTA per batch, 512 threads.
// ---------------------------------------------------------------------------
__global__ __launch_bounds__(512) void final_kernel(float* __restrict__ out) {
    int b = blockIdx.x, t = threadIdx.x;
    int base = b * NN;

    __shared__ unsigned s_mask[NN * 10];
    __shared__ unsigned s_valid[10];
    __shared__ int s_list[NN];
    __shared__ int s_M;
    __shared__ float s_score[NN];
    __shared__ int s_lab[NN];
    __shared__ float s_box[NN][4];
    __shared__ int s_ord[NN];

    for (int idx = t; idx < NN * 10; idx += 512) s_mask[idx] = g_mask[base * 10 + idx];
    if (t < NN) {
        s_score[t] = g_sscore[base + t];
        s_lab[t] = g_slab[base + t];
        s_ord[t] = g_sorder[base + t];
        s_box[t][0] = g_sbox[(base + t) * 4 + 0];
        s_box[t][1] = g_sbox[(base + t) * 4 + 1];
        s_box[t][2] = g_sbox[(base + t) * 4 + 2];
        s_box[t][3] = g_sbox[(base + t) * 4 + 3];
    }
    if (t < 320) {  // warps 0..9 fully active
        unsigned pred = (t < NN) && (s_score[t] > 0.01f);  // own value, no sync needed
        unsigned vw = __ballot_sync(0xffffffffu, pred);
        if ((t & 31) == 0) s_valid[t >> 5] = vw;
    }
    __syncthreads();

    if (t == 0) {
        unsigned rem[10];
#pragma unroll
        for (int k = 0; k < 10; k++) rem[k] = s_valid[k];
        int m = 0;
        for (int wd = 0; wd < 10; wd++) {
            while (rem[wd]) {
                int bit = __ffs(rem[wd]) - 1;
                int i = wd * 32 + bit;
                rem[wd] &= ~(1u << bit);
                s_list[m++] = i;
#pragma unroll
                for (int k = 0; k < 10; k++) rem[k] &= ~s_mask[i * 10 + k];
            }
        }
        s_M = m;
    }
    __syncthreads();
    int M = s_M;

    // --- outputs: [fl | fb | fs | akpts | vkeep], all float32 ---
    const int OUT_FB = BB * NN;                    // 1200
    const int OUT_FS = OUT_FB + BB * NN * 4;       // 6000
    const int OUT_KP = OUT_FS + BB * NN;           // 7200
    const int OUT_VK = OUT_KP + BB * NN * KK * 3;  // 68400

    if (t < NN) {
        int p = t;
        if (p < M) {
            int i = s_list[p];
            out[base + p] = (float)s_lab[i];
            out[OUT_FS + base + p] = s_score[i];  // kept => valid => unmasked score
            out[OUT_VK + base + p] = 1.0f;
            out[OUT_FB + (base + p) * 4 + 0] = s_box[i][0];
            out[OUT_FB + (base + p) * 4 + 1] = s_box[i][1];
            out[OUT_FB + (base + p) * 4 + 2] = s_box[i][2];
            out[OUT_FB + (base + p) * 4 + 3] = s_box[i][3];
        } else {
            out[base + p] = -1.0f;
            out[OUT_FS + base + p] = 0.0f;
            out[OUT_VK + base + p] = 0.0f;
            out[OUT_FB + (base + p) * 4 + 0] = 0.0f;
            out[OUT_FB + (base + p) * 4 + 1] = 0.0f;
            out[OUT_FB + (base + p) * 4 + 2] = 0.0f;
            out[OUT_FB + (base + p) * 4 + 3] = 0.0f;
        }
    }
    for (int idx = t; idx < NN * KK * 3; idx += 512) {
        int p = idx / (KK * 3);
        int r = idx % (KK * 3);
        float val = 0.0f;
        if (p < M) {
            int i = s_list[p];
            int orig = s_ord[i];
            int k = r / 3, c = r % 3;
            float kv = g_kpts[(((size_t)b * NN + orig) * KK + k) * 3 + c];
            if (c == 0) {
                val = s_box[i][0] + kv * (s_box[i][2] - s_box[i][0]);
            } else if (c == 1) {
                val = s_box[i][1] + kv * (s_box[i][3] - s_box[i][1]);
            } else {
                val = kv;
            }
        }
        out[OUT_KP + (size_t)b * NN * KK * 3 + idx] = val;
    }
}

extern "C" void kernel_launch(void* const* d_in, const int* in_sizes, int n_in,
                              void* d_out, int out_size) {
    const float* logits = (const float*)d_in[0];  // (4,300,80)
    const float* boxes = (const float*)d_in[1];   // (4,300,4)
    const float* hm = (const float*)d_in[2];      // (4,300,17,64,64)
    const float* off = (const float*)d_in[3];     // (4,300,17,2)
    const float* sizes = (const float*)d_in[4];   // (4,2)
    float* out = (float*)d_out;

    hm_kernel<<<BB * NN * KK, 128>>>(hm, off);
    prep_kernel<<<(BB * NN + 7) / 8, 256>>>(logits, boxes, sizes);
    sort_kernel<<<BB, 512>>>();
    iou_kernel<<<BB * NN, 320>>>();
    final_kernel<<<BB, 512>>>(out);
}